// round 4
// baseline (speedup 1.0000x reference)
#include <cuda_runtime.h>
#include <cuda_bf16.h>
#include <cstdint>

#define S_LEN  262144
#define NDIM   128
#define TILE   128
#define NTILES (S_LEN / TILE)   // 2048
#define GRID   148

// ---------------- device scratch ----------------
__device__ float g_W[NDIM * NDIM];                        // M (fp32, for l1)
__device__ __align__(16) char g_Bsw[NDIM * NDIM * 2];     // B[t][i]=bf16(M[i][t]), swizzled layout
__device__ float g_partials[GRID];

// ---------------- smem byte offsets ----------------
#define STG_OFF   0        // fp32 staging, 128 rows x 512B = 65536
#define HI_OFF    65536    // bf16 hi plane, 128 x 256B = 32768 (swizzled)
#define LO_OFF    98304    // bf16 lo plane, 32768
#define B_OFF     131072   // B bf16, 32768 (swizzled)
#define ROW_OFF   163840   // rowsum[128] fp32
#define NEXT_OFF  164352   // boundary row fp32, 2 x 512B
#define RED_OFF   165376   // reduction, 256 fp32
#define SMEM_BYTES 166400

// ---------------- helpers ----------------
__device__ __forceinline__ uint32_t smem_u32(const void* p) {
    uint32_t a;
    asm("{ .reg .u64 t; cvta.to.shared.u64 t, %1; cvt.u32.u64 %0, t; }" : "=r"(a) : "l"(p));
    return a;
}
__device__ __forceinline__ uint32_t bf2(float xh, float xl) {
    uint32_t r;
    asm("cvt.rn.bf16x2.f32 %0, %1, %2;" : "=r"(r) : "f"(xh), "f"(xl));
    return r;
}
__device__ __forceinline__ float lo_f(uint32_t p) { return __uint_as_float(p << 16); }
__device__ __forceinline__ float hi_f(uint32_t p) { return __uint_as_float(p & 0xffff0000u); }

__device__ __forceinline__ uint32_t lds32(uint32_t a) {
    uint32_t v;
    asm volatile("ld.shared.b32 %0, [%1];" : "=r"(v) : "r"(a));
    return v;
}
__device__ __forceinline__ float2 lds64f(uint32_t a) {
    float2 v;
    asm volatile("ld.shared.v2.f32 {%0,%1}, [%2];" : "=f"(v.x), "=f"(v.y) : "r"(a));
    return v;
}
__device__ __forceinline__ float4 lds128f(uint32_t a) {
    float4 v;
    asm volatile("ld.shared.v4.f32 {%0,%1,%2,%3}, [%4];"
                 : "=f"(v.x), "=f"(v.y), "=f"(v.z), "=f"(v.w) : "r"(a));
    return v;
}
__device__ __forceinline__ void sts64(uint32_t a, uint64_t v) {
    asm volatile("st.shared.b64 [%0], %1;" :: "r"(a), "l"(v));
}
__device__ __forceinline__ void ldsm4(uint32_t* r, uint32_t a) {
    asm volatile("ldmatrix.sync.aligned.m8n8.x4.shared.b16 {%0,%1,%2,%3}, [%4];"
                 : "=r"(r[0]), "=r"(r[1]), "=r"(r[2]), "=r"(r[3]) : "r"(a));
}
__device__ __forceinline__ void cpa16(uint32_t dst, const void* src) {
    asm volatile("cp.async.cg.shared.global [%0], [%1], 16;" :: "r"(dst), "l"(src));
}
__device__ __forceinline__ void cpa_commit() { asm volatile("cp.async.commit_group;" ::: "memory"); }
__device__ __forceinline__ void cpa_wait0()  { asm volatile("cp.async.wait_group 0;" ::: "memory"); }

__device__ __forceinline__ void mma_bf16(float* d, const uint32_t* a, uint32_t b0, uint32_t b1) {
    asm volatile(
        "mma.sync.aligned.m16n8k16.row.col.f32.bf16.bf16.f32 "
        "{%0,%1,%2,%3}, {%4,%5,%6,%7}, {%8,%9}, {%0,%1,%2,%3};"
        : "+f"(d[0]), "+f"(d[1]), "+f"(d[2]), "+f"(d[3])
        : "r"(a[0]), "r"(a[1]), "r"(a[2]), "r"(a[3]), "r"(b0), "r"(b1));
}
__device__ __forceinline__ float softplusf(float x) {
    if (x > 15.0f) return x;
    return __logf(1.0f + __expf(x));
}
// swizzled byte offset inside a 128x(128 bf16) plane: row r, element k
__device__ __forceinline__ uint32_t psw(int r, int k) {
    return (uint32_t)(r * 256) + (uint32_t)((((k >> 3) ^ (r & 7)) << 4) + ((k & 7) << 1));
}

// ---------------- kernel A: M = W_K^T @ W_Q ----------------
__global__ void __launch_bounds__(128, 1)
compute_W_kernel(const float* __restrict__ WQ, const float* __restrict__ WK) {
    __shared__ float swk[NDIM];
    const int i = blockIdx.x;     // M row (k index of B)
    const int t = threadIdx.x;    // M col (n index of B)
    swk[t] = WK[t * NDIM + i];
    __syncthreads();
    float acc = 0.f;
#pragma unroll 8
    for (int j = 0; j < NDIM; ++j)
        acc = fmaf(swk[j], WQ[j * NDIM + t], acc);
    g_W[i * NDIM + t] = acc;
    *(__nv_bfloat16*)(g_Bsw + psw(t, i)) = __float2bfloat16(acc);
}

// ---------------- fused persistent kernel ----------------
extern __shared__ char dsm[];

__device__ __forceinline__ void issue_prefetch(const float* __restrict__ In, int tile,
                                               uint32_t sb, int slot, int tid) {
    const char* src = (const char*)(In + (size_t)tile * TILE * NDIM);
#pragma unroll
    for (int j = 0; j < 16; ++j) {
        const int idx = tid + 256 * j;
        const int r = idx >> 5, c = idx & 31;
        cpa16(sb + STG_OFF + r * 512 + c * 16, src + r * 512 + c * 16);
    }
    if (tid < 32) {
        size_t nr = (size_t)tile * TILE + TILE;
        if (nr >= S_LEN) nr = 0;     // clamped; unused (masked)
        cpa16(sb + NEXT_OFF + slot * 512 + tid * 16, (const char*)(In + nr * NDIM) + tid * 16);
    }
    cpa_commit();
}

__device__ __forceinline__ void convert_tile(uint32_t sb, int tid) {
    const int lane = tid & 31;
    float* sRow = (float*)(dsm + ROW_OFF);
#pragma unroll 4
    for (int j = 0; j < 16; ++j) {
        const int r = (tid >> 5) + 8 * j;
        const float4 v = lds128f(sb + STG_OFF + r * 512 + lane * 16);
        float s = (v.x + v.y) + (v.z + v.w);
#pragma unroll
        for (int o = 16; o; o >>= 1) s += __shfl_xor_sync(0xffffffffu, s, o);
        if (lane == 0) sRow[r] = s;
        const uint32_t h01 = bf2(v.y, v.x), h23 = bf2(v.w, v.z);
        const uint32_t l01 = bf2(v.y - hi_f(h01), v.x - lo_f(h01));
        const uint32_t l23 = bf2(v.w - hi_f(h23), v.z - lo_f(h23));
        const uint32_t off = (uint32_t)(r * 256) +
                             ((((lane >> 1) ^ (r & 7)) << 4) + ((lane & 1) << 3));
        sts64(sb + HI_OFF + off, ((uint64_t)h23 << 32) | h01);
        sts64(sb + LO_OFF + off, ((uint64_t)l23 << 32) | l01);
    }
}

__global__ void __launch_bounds__(256, 1)
fused_kernel(const float* __restrict__ In) {
    const uint32_t sb = smem_u32(dsm);
    const int tid  = threadIdx.x;
    const int lane = tid & 31;
    const int w    = tid >> 5;
    const int m0   = (w & 3) << 5;      // warp tile 32m x 64n
    const int n0   = (w >> 2) << 6;
    const int g    = lane >> 2;
    const int q    = lane & 3;

    // stage B (already swizzled in global)
    {
        const float4* src = (const float4*)g_Bsw;
        float4* dst = (float4*)(dsm + B_OFF);
#pragma unroll
        for (int k = tid; k < 2048; k += 256) dst[k] = src[k];
    }

    // per-lane ldmatrix row precomputes
    const int lrow = lane & 15;
    const int kbit = lane >> 4;           // selects k-block half
    uint32_t aoffA[2]; int rxA[2];
#pragma unroll
    for (int mh = 0; mh < 2; ++mh) {
        const int r = m0 + 16 * mh + lrow;
        aoffA[mh] = (uint32_t)(r * 256);
        rxA[mh] = r & 7;
    }
    uint32_t boffB[4]; int rxB[4];
#pragma unroll
    for (int e = 0; e < 4; ++e) {
        const int r = n0 + 16 * e + lrow;
        boffB[e] = (uint32_t)(r * 256);
        rxB[e] = r & 7;
    }

    const int bx = blockIdx.x;
    const int nt = (NTILES - bx + GRID - 1) / GRID;
    const float* sRow  = (const float*)(dsm + ROW_OFF);

    issue_prefetch(In, bx, sb, 0, tid);

    float loss = 0.f;
    for (int i = 0; i < nt; ++i) {
        const int tile = bx + i * GRID;
        cpa_wait0();
        __syncthreads();                    // staging ready; prev mainloop done
        convert_tile(sb, tid);
        __syncthreads();                    // planes + rowsums ready
        if (i + 1 < nt) issue_prefetch(In, bx + (i + 1) * GRID, sb, (i + 1) & 1, tid);

        // -------- mainloop: 8 k-steps, ldmatrix + HMMA --------
        float dacc[2][8][4];
#pragma unroll
        for (int mh = 0; mh < 2; ++mh)
#pragma unroll
            for (int nf = 0; nf < 8; ++nf)
#pragma unroll
                for (int j = 0; j < 4; ++j) dacc[mh][nf][j] = 0.f;

#pragma unroll
        for (int ks = 0; ks < 8; ++ks) {
            uint32_t ah[2][4], al[2][4], bb[4][4];
#pragma unroll
            for (int mh = 0; mh < 2; ++mh) {
                const uint32_t u = (uint32_t)(((2 * ks + kbit) ^ rxA[mh]) << 4);
                ldsm4(ah[mh], sb + HI_OFF + aoffA[mh] + u);
                ldsm4(al[mh], sb + LO_OFF + aoffA[mh] + u);
            }
#pragma unroll
            for (int e = 0; e < 4; ++e) {
                const uint32_t u = (uint32_t)(((2 * ks + kbit) ^ rxB[e]) << 4);
                ldsm4(bb[e], sb + B_OFF + boffB[e] + u);
            }
#pragma unroll
            for (int e = 0; e < 4; ++e)
#pragma unroll
                for (int h = 0; h < 2; ++h) {
                    const uint32_t b0 = h ? bb[e][1] : bb[e][0];
                    const uint32_t b1 = h ? bb[e][3] : bb[e][2];
#pragma unroll
                    for (int mh = 0; mh < 2; ++mh) {
                        mma_bf16(dacc[mh][2 * e + h], ah[mh], b0, b1);
                        mma_bf16(dacc[mh][2 * e + h], al[mh], b0, b1);
                    }
                }
        }

        // -------- epilogue --------
        const size_t base = (size_t)tile * TILE;
        const uint32_t nextB = sb + NEXT_OFF + (uint32_t)(i & 1) * 512;
#pragma unroll
        for (int mh = 0; mh < 2; ++mh) {
            const int rowA = m0 + 16 * mh + g;       // <= 119
            const int rowB = rowA + 8;               // <= 127
            const float rsA = sRow[rowA];
            const float rsB = sRow[rowB];
            const bool vB = (base + rowB) < (size_t)(S_LEN - 1);
            const int rA1 = rowA + 1;                // <= 120, in-plane
            const int rB1 = rowB + 1;                // may be 128 -> boundary
#pragma unroll
            for (int nf = 0; nf < 8; ++nf) {
                const int col = n0 + 8 * nf + 2 * q;
                // next-row values (hi+lo reconstruct)
                const uint32_t oa = psw(rA1, col);
                const uint32_t ha = lds32(sb + HI_OFF + oa);
                const uint32_t la = lds32(sb + LO_OFF + oa);
                const float nxa0 = lo_f(ha) + lo_f(la);
                const float nxa1 = hi_f(ha) + hi_f(la);
                float nxb0, nxb1;
                if (rB1 < TILE) {
                    const uint32_t ob = psw(rB1, col);
                    const uint32_t hb = lds32(sb + HI_OFF + ob);
                    const uint32_t lb = lds32(sb + LO_OFF + ob);
                    nxb0 = lo_f(hb) + lo_f(lb);
                    nxb1 = hi_f(hb) + hi_f(lb);
                } else {
                    const float2 nb = lds64f(nextB + col * 4);
                    nxb0 = nb.x; nxb1 = nb.y;
                }
                const float* d = dacc[mh][nf];
                float t0 = fmaf(softplusf(d[0]), rsA, -nxa0);
                float t1 = fmaf(softplusf(d[1]), rsA, -nxa1);
                loss = fmaf(t0, t0, loss);
                loss = fmaf(t1, t1, loss);
                if (vB) {
                    float t2 = fmaf(softplusf(d[2]), rsB, -nxb0);
                    float t3 = fmaf(softplusf(d[3]), rsB, -nxb1);
                    loss = fmaf(t2, t2, loss);
                    loss = fmaf(t3, t3, loss);
                }
            }
        }
        __syncthreads();   // epilogue readers done before next convert overwrites
    }

    // deterministic CTA reduction
    float* sRed = (float*)(dsm + RED_OFF);
    sRed[tid] = loss;
    __syncthreads();
#pragma unroll
    for (int o = 128; o; o >>= 1) {
        if (tid < o) sRed[tid] += sRed[tid + o];
        __syncthreads();
    }
    if (tid == 0) g_partials[blockIdx.x] = sRed[0];
}

// ---------------- finalize ----------------
__global__ void finalize_kernel(float* __restrict__ out) {
    __shared__ double red[256];
    const int tid = threadIdx.x;

    double s = 0.0;
    for (int k = tid; k < GRID; k += 256) s += (double)g_partials[k];
    red[tid] = s;
    __syncthreads();
    for (int o = 128; o; o >>= 1) {
        if (tid < o) red[tid] += red[tid + o];
        __syncthreads();
    }
    if (tid == 0)
        out[0] = (float)(red[0] / ((double)(S_LEN - 1) * (double)NDIM));
    __syncthreads();

    double l1 = 0.0;
    for (int k = tid; k < NDIM * NDIM; k += 256) {
        const float w = g_W[k];
        l1 += (double)(1.0f / (1.0f + __expf(-w)));
    }
    red[tid] = l1;
    __syncthreads();
    for (int o = 128; o; o >>= 1) {
        if (tid < o) red[tid] += red[tid + o];
        __syncthreads();
    }
    if (tid == 0) out[1] = (float)red[0];
}

// ---------------- launch ----------------
extern "C" void kernel_launch(void* const* d_in, const int* in_sizes, int n_in,
                              void* d_out, int out_size) {
    const float* In = (const float*)d_in[0];
    const float* WQ = (const float*)d_in[1];
    const float* WK = (const float*)d_in[2];
    float* out = (float*)d_out;

    compute_W_kernel<<<NDIM, NDIM>>>(WQ, WK);

    cudaFuncSetAttribute(fused_kernel,
                         cudaFuncAttributeMaxDynamicSharedMemorySize, SMEM_BYTES);
    fused_kernel<<<GRID, 256, SMEM_BYTES>>>(In);

    finalize_kernel<<<1, 256>>>(out);
}

// round 5
// speedup vs baseline: 1.7541x; 1.7541x over previous
#include <cuda_runtime.h>
#include <cuda_bf16.h>
#include <cstdint>

#define S_LEN  262144
#define NDIM   128
#define TILE   128
#define NTILES 2048
#define GRID   148

// ---------------- device scratch ----------------
__device__ float g_W[NDIM * NDIM];                          // M (fp32, for l1)
__device__ __align__(16) __nv_bfloat16 g_Bsw[NDIM * NDIM];  // B[t][k]=bf16(M[k][t]), XOR-swizzled
__device__ float g_partials[GRID];

// ---------------- smem byte offsets ----------------
#define STG0   0          // fp32 staging buf0: 128 rows x 512B = 65536
#define STG1   65536      // buf1
#define BOFF   131072     // B bf16 swizzled: 32768
#define NEXTO  163840     // boundary rows fp32: 2 x 512
#define REDO   164864     // reduction: 256 fp32
#define SMEM_BYTES 165888

// ---------------- helpers ----------------
__device__ __forceinline__ uint32_t smem_u32(const void* p) {
    uint32_t a;
    asm("{ .reg .u64 t; cvta.to.shared.u64 t, %1; cvt.u32.u64 %0, t; }" : "=r"(a) : "l"(p));
    return a;
}
__device__ __forceinline__ uint32_t bf2(float xh, float xl) {
    uint32_t r;
    asm("cvt.rn.bf16x2.f32 %0, %1, %2;" : "=r"(r) : "f"(xh), "f"(xl));
    return r;
}
__device__ __forceinline__ float4 lds128f(uint32_t a) {
    float4 v;
    asm volatile("ld.shared.v4.f32 {%0,%1,%2,%3}, [%4];"
                 : "=f"(v.x), "=f"(v.y), "=f"(v.z), "=f"(v.w) : "r"(a));
    return v;
}
__device__ __forceinline__ float2 lds64f(uint32_t a) {
    float2 v;
    asm volatile("ld.shared.v2.f32 {%0,%1}, [%2];" : "=f"(v.x), "=f"(v.y) : "r"(a));
    return v;
}
__device__ __forceinline__ uint2 lds64u(uint32_t a) {
    uint2 v;
    asm volatile("ld.shared.v2.b32 {%0,%1}, [%2];" : "=r"(v.x), "=r"(v.y) : "r"(a));
    return v;
}
__device__ __forceinline__ void cpa16(uint32_t dst, const void* src) {
    asm volatile("cp.async.cg.shared.global [%0], [%1], 16;" :: "r"(dst), "l"(src));
}
__device__ __forceinline__ void cpa_commit() { asm volatile("cp.async.commit_group;" ::: "memory"); }
__device__ __forceinline__ void cpa_wait0()  { asm volatile("cp.async.wait_group 0;" ::: "memory"); }

__device__ __forceinline__ void mma_bf16(float* d, const uint32_t* a, uint32_t b0, uint32_t b1) {
    asm volatile(
        "mma.sync.aligned.m16n8k16.row.col.f32.bf16.bf16.f32 "
        "{%0,%1,%2,%3}, {%4,%5,%6,%7}, {%8,%9}, {%0,%1,%2,%3};"
        : "+f"(d[0]), "+f"(d[1]), "+f"(d[2]), "+f"(d[3])
        : "r"(a[0]), "r"(a[1]), "r"(a[2]), "r"(a[3]), "r"(b0), "r"(b1));
}
__device__ __forceinline__ float softplusf(float x) {
    const float l = __logf(1.0f + __expf(x));
    return (x > 15.0f) ? x : l;
}
// B swizzled element offset (bytes): col t, k index
__device__ __forceinline__ uint32_t bswz(int t, int k) {
    return (uint32_t)(t * 256 + ((((k >> 2) ^ ((t & 7) << 2))) << 3) + (k & 3) * 2);
}

// ---------------- kernel A: M = W_K^T @ W_Q ----------------
extern __shared__ float wsmem[];
__global__ void __launch_bounds__(256, 1)
compute_W_kernel(const float* __restrict__ WQ, const float* __restrict__ WK) {
    float* sWQ  = wsmem;                 // 128x128
    float* sWK8 = wsmem + NDIM * NDIM;   // 128x8
    const int tid = threadIdx.x;
    const int i0  = blockIdx.x * 8;
    {
        const float4* src = (const float4*)WQ;
        float4* dst = (float4*)sWQ;
#pragma unroll
        for (int k = tid; k < NDIM * NDIM / 4; k += 256) dst[k] = src[k];
    }
    for (int k = tid; k < NDIM * 8; k += 256) {
        const int j = k >> 3, u = k & 7;
        sWK8[k] = WK[j * NDIM + i0 + u];
    }
    __syncthreads();
    const int t  = tid & 127;
    const int ib = (tid >> 7) * 4;
    float acc[4] = {0.f, 0.f, 0.f, 0.f};
#pragma unroll 4
    for (int j = 0; j < NDIM; ++j) {
        const float wq = sWQ[j * NDIM + t];
#pragma unroll
        for (int u = 0; u < 4; ++u) acc[u] = fmaf(sWK8[j * 8 + ib + u], wq, acc[u]);
    }
#pragma unroll
    for (int u = 0; u < 4; ++u) {
        const int i = i0 + ib + u;                   // k index
        g_W[i * NDIM + t] = acc[u];
        *(__nv_bfloat16*)((char*)g_Bsw + bswz(t, i)) = __float2bfloat16(acc[u]);
    }
}

// ---------------- fused persistent kernel ----------------
extern __shared__ char dsm[];

__device__ __forceinline__ void issue_prefetch(const float* __restrict__ In, int tile,
                                               uint32_t sb, int slot, int tid) {
    const char* src = (const char*)(In + (size_t)tile * TILE * NDIM);
    const uint32_t stg = sb + (slot ? STG1 : STG0);
#pragma unroll
    for (int j = 0; j < 16; ++j) {
        const int idx = tid + 256 * j;           // 4096 16B chunks
        const int r = idx >> 5, c = idx & 31;
        cpa16(stg + r * 512 + ((c ^ ((r & 1) << 2)) << 4), src + r * 512 + c * 16);
    }
    if (tid < 32) {
        size_t nr = (size_t)tile * TILE + TILE;
        if (nr >= S_LEN) nr = 0;                  // clamped; value masked out
        cpa16(sb + NEXTO + slot * 512 + tid * 16, (const char*)(In + nr * NDIM) + tid * 16);
    }
    cpa_commit();
}

__global__ void __launch_bounds__(256)
fused_kernel(const float* __restrict__ In) {
    const uint32_t sb = smem_u32(dsm);
    const int tid  = threadIdx.x;
    const int lane = tid & 31;
    const int w    = tid >> 5;
    const int m0   = (w & 3) << 5;     // warp tile: 32m x 64n (grid 4m x 2n)
    const int n0   = (w >> 2) << 6;
    const int g    = lane >> 2;
    const int q    = lane & 3;

    // stage B (global already swizzled) -> smem
    {
        const float4* src = (const float4*)g_Bsw;
        float4* dst = (float4*)(dsm + BOFF);
#pragma unroll
        for (int k = tid; k < 2048; k += 256) dst[k] = src[k];
    }

    const int rA0 = m0 + g;            // rows rA0, rA0+8, rA0+16, rA0+24
    const uint32_t xA = (uint32_t)((g & 1) << 2);
    const uint32_t xB = (uint32_t)(g << 2);
    uint32_t baseB[8];
#pragma unroll
    for (int nf = 0; nf < 8; ++nf) baseB[nf] = sb + BOFF + (uint32_t)(n0 + 8 * nf + g) * 256;

    const int bx = blockIdx.x;
    const int nt = (NTILES - bx + GRID - 1) / GRID;

    issue_prefetch(In, bx, sb, 0, tid);

    float loss = 0.f;
    for (int i = 0; i < nt; ++i) {
        const int tile = bx + i * GRID;
        cpa_wait0();
        __syncthreads();                 // buf(i&1) ready; all warps done with prev compute
        if (i + 1 < nt) issue_prefetch(In, bx + (i + 1) * GRID, sb, (i + 1) & 1, tid);

        const uint32_t stg = sb + ((i & 1) ? STG1 : STG0);
        const uint32_t bA0 = stg + (uint32_t)rA0 * 512;          // row rA0
        const uint32_t bA1 = bA0 + 16 * 512;                     // row rA0+16

        float dacc[2][8][4];
#pragma unroll
        for (int mh = 0; mh < 2; ++mh)
#pragma unroll
            for (int nf = 0; nf < 8; ++nf)
#pragma unroll
                for (int j = 0; j < 4; ++j) dacc[mh][nf][j] = 0.f;
        float rsum[4] = {0.f, 0.f, 0.f, 0.f};

#pragma unroll
        for (int ks = 0; ks < 8; ++ks) {
            const uint32_t c = (uint32_t)(4 * ks + q);
            const uint32_t offA = ((c ^ xA) << 4);
            const float4 v00 = lds128f(bA0 + offA);              // row rA0
            const float4 v01 = lds128f(bA0 + 8 * 512 + offA);    // row rA0+8
            const float4 v10 = lds128f(bA1 + offA);              // row rA0+16
            const float4 v11 = lds128f(bA1 + 8 * 512 + offA);    // row rA0+24
            rsum[0] += (v00.x + v00.y) + (v00.z + v00.w);
            rsum[1] += (v01.x + v01.y) + (v01.z + v01.w);
            rsum[2] += (v10.x + v10.y) + (v10.z + v10.w);
            rsum[3] += (v11.x + v11.y) + (v11.z + v11.w);
            uint32_t a0[4], a1[4];
            a0[0] = bf2(v00.y, v00.x); a0[1] = bf2(v01.y, v01.x);
            a0[2] = bf2(v00.w, v00.z); a0[3] = bf2(v01.w, v01.z);
            a1[0] = bf2(v10.y, v10.x); a1[1] = bf2(v11.y, v11.x);
            a1[2] = bf2(v10.w, v10.z); a1[3] = bf2(v11.w, v11.z);
            const uint32_t offB = ((c ^ xB) << 3);
#pragma unroll
            for (int nf = 0; nf < 8; ++nf) {
                const uint2 b = lds64u(baseB[nf] + offB);
                mma_bf16(dacc[0][nf], a0, b.x, b.y);
                mma_bf16(dacc[1][nf], a1, b.x, b.y);
            }
        }

        // quad-reduce rowsums (lanes of a quad cover the full 128-k row)
#pragma unroll
        for (int j = 0; j < 4; ++j) {
            rsum[j] += __shfl_xor_sync(0xffffffffu, rsum[j], 1);
            rsum[j] += __shfl_xor_sync(0xffffffffu, rsum[j], 2);
        }

        // -------- epilogue --------
        const size_t base = (size_t)tile * TILE;
        const uint32_t nextB = sb + NEXTO + (uint32_t)(i & 1) * 512;
        const uint32_t xN = (uint32_t)(((g + 1) & 1) << 2);     // parity of rows rA+1
#pragma unroll
        for (int mh = 0; mh < 2; ++mh) {
            const int rA = m0 + 16 * mh + g;        // <= 119
            const int rB = rA + 8;                  // <= 127
            const float rsA = rsum[2 * mh];
            const float rsB = rsum[2 * mh + 1];
            const bool vB = (base + rB) < (size_t)(S_LEN - 1);
#pragma unroll
            for (int nf = 0; nf < 8; ++nf) {
                const int col0 = n0 + 8 * nf + 2 * q;
                const uint32_t off = (((uint32_t)(col0 >> 2) ^ xN) << 4) + ((col0 & 3) << 2);
                const float2 nxa = lds64f(stg + (uint32_t)(rA + 1) * 512 + off);
                const float2 nxb = (rB < TILE - 1)
                                       ? lds64f(stg + (uint32_t)(rB + 1) * 512 + off)
                                       : lds64f(nextB + col0 * 4);
                const float* d = dacc[mh][nf];
                const float t0 = fmaf(softplusf(d[0]), rsA, -nxa.x);
                const float t1 = fmaf(softplusf(d[1]), rsA, -nxa.y);
                loss = fmaf(t0, t0, loss);
                loss = fmaf(t1, t1, loss);
                if (vB) {
                    const float t2 = fmaf(softplusf(d[2]), rsB, -nxb.x);
                    const float t3 = fmaf(softplusf(d[3]), rsB, -nxb.y);
                    loss = fmaf(t2, t2, loss);
                    loss = fmaf(t3, t3, loss);
                }
            }
        }
    }

    // deterministic CTA reduction
    float* sRed = (float*)(dsm + REDO);
    __syncthreads();
    sRed[tid] = loss;
    __syncthreads();
#pragma unroll
    for (int o = 128; o; o >>= 1) {
        if (tid < o) sRed[tid] += sRed[tid + o];
        __syncthreads();
    }
    if (tid == 0) g_partials[blockIdx.x] = sRed[0];
}

// ---------------- finalize ----------------
__global__ void finalize_kernel(float* __restrict__ out) {
    __shared__ double red[256];
    const int tid = threadIdx.x;

    double s = 0.0;
    for (int k = tid; k < GRID; k += 256) s += (double)g_partials[k];
    red[tid] = s;
    __syncthreads();
    for (int o = 128; o; o >>= 1) {
        if (tid < o) red[tid] += red[tid + o];
        __syncthreads();
    }
    if (tid == 0)
        out[0] = (float)(red[0] / ((double)(S_LEN - 1) * (double)NDIM));
    __syncthreads();

    double l1 = 0.0;
    for (int k = tid; k < NDIM * NDIM; k += 256) {
        const float w = g_W[k];
        l1 += (double)(1.0f / (1.0f + __expf(-w)));
    }
    red[tid] = l1;
    __syncthreads();
    for (int o = 128; o; o >>= 1) {
        if (tid < o) red[tid] += red[tid + o];
        __syncthreads();
    }
    if (tid == 0) out[1] = (float)red[0];
}

// ---------------- launch ----------------
extern "C" void kernel_launch(void* const* d_in, const int* in_sizes, int n_in,
                              void* d_out, int out_size) {
    const float* In = (const float*)d_in[0];
    const float* WQ = (const float*)d_in[1];
    const float* WK = (const float*)d_in[2];
    float* out = (float*)d_out;

    const int wq_smem = (NDIM * NDIM + NDIM * 8) * sizeof(float);
    cudaFuncSetAttribute(compute_W_kernel,
                         cudaFuncAttributeMaxDynamicSharedMemorySize, wq_smem);
    compute_W_kernel<<<16, 256, wq_smem>>>(WQ, WK);

    cudaFuncSetAttribute(fused_kernel,
                         cudaFuncAttributeMaxDynamicSharedMemorySize, SMEM_BYTES);
    fused_kernel<<<GRID, 256, SMEM_BYTES>>>(In);

    finalize_kernel<<<1, 256>>>(out);
}